// round 15
// baseline (speedup 1.0000x reference)
#include <cuda_runtime.h>
#include <math.h>

#define NSZ 192
#define NC  16
#define MXY 32
#define NLINE (NC*NSZ)       // 3072
#define NROW  (NC*NSZ*NSZ)   // 589824

// ---------------- twiddle master table + scratch -----------------------------
static __device__ float2 Tm[NSZ];   // (cos, sin) of 2*pi*p/192

static __device__ __align__(16) float2 X1g[(size_t)NROW * 16];            // (c,x,y,kz)
static __device__ __align__(16) float2 X2g[(size_t)NLINE * MXY * 16];     // (c,x,ky,kz)
static __device__ __align__(16) float2 X3g[(size_t)NC * MXY * MXY * 16];  // (i,kx,ky,kz)
static __device__ __align__(16) float2 Y3g[(size_t)NC * MXY * MXY * 16];  // (o,kx,ky,kz)
static __device__ __align__(16) float2 Y2g[(size_t)NLINE * MXY * 16];     // (c,x,ky,kz)
static __device__ __align__(16) float2 Y1g[(size_t)NROW * 16];            // (c,x,y,kz)

__device__ __forceinline__ int kmap(int j) { return j < 16 ? j : j + 160; }

__global__ void k_init() {
  int p = threadIdx.x;
  if (p < NSZ) {
    float s, c;
    sincosf(6.283185307179586f * (float)p / 192.0f, &s, &c);
    Tm[p] = make_float2(c, s);
  }
}

// ---------------- S1: z-DFT, real -> 16 modes, double fold -------------------
// Fold1 (z<->z+96): s/d by k parity. Fold2 (t<->96-t):
//   Re[k even] = sum_{u<48} se[u] cos(kuT) + s48*(-1)^m           (k=2m)
//   Im[k even] = -sum so[u] sin(kuT)
//   Re[k odd]  = sum do[u] cos(kuT)
//   Im[k odd]  = -sum de[u] sin(kuT) - d48*(-1)^m                 (k=2m+1)
// block: 128 thr, 256 rows; thread = (tx: 4 k's, ty: 32) x 8 rows
__global__ void __launch_bounds__(128) k_s1(const float* __restrict__ xg) {
  __shared__ float se_s[8][257], so_s[8][257], de_s[8][257], do_s[8][257];
  __shared__ float2 tws[8][16];
  __shared__ float s48s[256], d48s[256];
  int tid = threadIdx.x;
  int tx = tid & 3, ty = tid >> 2;
  int rowBase = blockIdx.x * 256;

  for (int i = tid; i < 256; i += 128) {
    const float* xr = xg + (size_t)(rowBase + i) * NSZ;
    float a = xr[48], b = xr[144];
    s48s[i] = a + b;  d48s[i] = a - b;
  }

  float2 acc[8][4];
#pragma unroll
  for (int j = 0; j < 8; j++)
#pragma unroll
    for (int q = 0; q < 4; q++) acc[j][q] = make_float2(0.f, 0.f);

  for (int uc = 0; uc < 48; uc += 8) {
    __syncthreads();
    {
      int ul = tid >> 4, k = tid & 15;
      tws[ul][k] = Tm[(k * (uc + ul)) % NSZ];
    }
    for (int i = tid; i < 512; i += 128) {
      int row = i >> 1, hh = i & 1;
      int u0 = uc + 4 * hh;
      const float* xr = xg + (size_t)(rowBase + row) * NSZ;
      float4 a = *(const float4*)(xr + u0);
      float4 b = *(const float4*)(xr + u0 + 96);
      float p0 = (u0 == 0) ? 0.f : xr[96 - u0];
      float p1 = xr[95 - u0];
      float p2 = xr[94 - u0];
      float p3 = xr[93 - u0];
      float q0 = (u0 == 0) ? 0.f : xr[192 - u0];
      float q1 = xr[191 - u0];
      float q2 = xr[190 - u0];
      float q3 = xr[189 - u0];
      int ub = 4 * hh;
      float s, d, sp, dp;
      s = a.x + b.x; d = a.x - b.x; sp = p0 + q0; dp = p0 - q0;
      se_s[ub+0][row] = s + sp; so_s[ub+0][row] = s - sp;
      de_s[ub+0][row] = d + dp; do_s[ub+0][row] = d - dp;
      s = a.y + b.y; d = a.y - b.y; sp = p1 + q1; dp = p1 - q1;
      se_s[ub+1][row] = s + sp; so_s[ub+1][row] = s - sp;
      de_s[ub+1][row] = d + dp; do_s[ub+1][row] = d - dp;
      s = a.z + b.z; d = a.z - b.z; sp = p2 + q2; dp = p2 - q2;
      se_s[ub+2][row] = s + sp; so_s[ub+2][row] = s - sp;
      de_s[ub+2][row] = d + dp; do_s[ub+2][row] = d - dp;
      s = a.w + b.w; d = a.w - b.w; sp = p3 + q3; dp = p3 - q3;
      se_s[ub+3][row] = s + sp; so_s[ub+3][row] = s - sp;
      de_s[ub+3][row] = d + dp; do_s[ub+3][row] = d - dp;
    }
    __syncthreads();
#pragma unroll 2
    for (int ul = 0; ul < 8; ul++) {
      float2 t0 = tws[ul][4 * tx + 0];
      float2 t1 = tws[ul][4 * tx + 1];
      float2 t2 = tws[ul][4 * tx + 2];
      float2 t3 = tws[ul][4 * tx + 3];
#pragma unroll
      for (int j = 0; j < 8; j++) {
        int r = ty + 32 * j;
        float sev = se_s[ul][r], sov = so_s[ul][r];
        float dev = de_s[ul][r], dov = do_s[ul][r];
        acc[j][0].x += sev * t0.x;  acc[j][0].y -= sov * t0.y;  // k even
        acc[j][1].x += dov * t1.x;  acc[j][1].y -= dev * t1.y;  // k odd
        acc[j][2].x += sev * t2.x;  acc[j][2].y -= sov * t2.y;
        acc[j][3].x += dov * t3.x;  acc[j][3].y -= dev * t3.y;
      }
    }
  }
#pragma unroll
  for (int j = 0; j < 8; j++) {
    int r = ty + 32 * j;
    float s48v = s48s[r], d48v = d48s[r];
#pragma unroll
    for (int q = 0; q < 4; q++) {
      int k = 4 * tx + q;
      float sgn = ((k >> 1) & 1) ? -1.f : 1.f;
      if ((k & 1) == 0) acc[j][q].x += sgn * s48v;
      else              acc[j][q].y -= sgn * d48v;
    }
    size_t base = (size_t)(rowBase + r) * 16 + 4 * tx;
    ((float4*)&X1g[base])[0] = make_float4(acc[j][0].x, acc[j][0].y, acc[j][1].x, acc[j][1].y);
    ((float4*)&X1g[base])[1] = make_float4(acc[j][2].x, acc[j][2].y, acc[j][3].x, acc[j][3].y);
  }
}

// ---------------- S2: y-DFT, complex, 32 ky modes, quad fold -----------------
// X[K] = sum_{t<48} u_{K mod 4}[t] w^{Kt}; u0=s1+s2, u2=s1-s2, u1=d1-i*d2, u3=d1+i*d2
// block: 128 thr = 4 lines x (kyg 8 x kzg 4); thread tile 4 ky (classes 0..3) x 4 kz
__global__ void __launch_bounds__(128) k_s2() {
  __shared__ __align__(16) float2 us[4][4][12][16];  // [line][cls][yl][kz]
  __shared__ float2 twy[12][32];
  int tid = threadIdx.x;
  int l = tid >> 5, lane = tid & 31;
  int kyg = lane >> 2, kzg = lane & 3;
  int lineBase = blockIdx.x * 4;

  float2 acc[4][4];
#pragma unroll
  for (int a = 0; a < 4; a++)
#pragma unroll
    for (int b = 0; b < 4; b++) acc[a][b] = make_float2(0.f, 0.f);

  for (int yc = 0; yc < 48; yc += 12) {
    __syncthreads();
    for (int i = tid; i < 12 * 32; i += 128) {
      int yl = i >> 5, ky = i & 31;
      twy[yl][ky] = Tm[(kmap(ky) * (yc + yl)) % NSZ];
    }
    for (int i = tid; i < 384; i += 128) {
      int li = i / 96, rem = i % 96;
      int yl = rem >> 3, v = rem & 7;
      size_t rb = ((size_t)(lineBase + li) * NSZ + yc + yl) * 16;
      float4 A = ((const float4*)&X1g[rb])[v];
      float4 B = ((const float4*)&X1g[rb + (size_t)48 * 16])[v];
      float4 C = ((const float4*)&X1g[rb + (size_t)96 * 16])[v];
      float4 D = ((const float4*)&X1g[rb + (size_t)144 * 16])[v];
      float4 s1 = make_float4(A.x + C.x, A.y + C.y, A.z + C.z, A.w + C.w);
      float4 s2 = make_float4(B.x + D.x, B.y + D.y, B.z + D.z, B.w + D.w);
      float4 d1 = make_float4(A.x - C.x, A.y - C.y, A.z - C.z, A.w - C.w);
      float4 d2 = make_float4(B.x - D.x, B.y - D.y, B.z - D.z, B.w - D.w);
      ((float4*)&us[li][0][yl][0])[v] =
          make_float4(s1.x + s2.x, s1.y + s2.y, s1.z + s2.z, s1.w + s2.w);
      ((float4*)&us[li][2][yl][0])[v] =
          make_float4(s1.x - s2.x, s1.y - s2.y, s1.z - s2.z, s1.w - s2.w);
      ((float4*)&us[li][1][yl][0])[v] =
          make_float4(d1.x + d2.y, d1.y - d2.x, d1.z + d2.w, d1.w - d2.z);
      ((float4*)&us[li][3][yl][0])[v] =
          make_float4(d1.x - d2.y, d1.y + d2.x, d1.z - d2.w, d1.w + d2.z);
    }
    __syncthreads();
#pragma unroll 2
    for (int yl = 0; yl < 12; yl++) {
#pragma unroll
      for (int a = 0; a < 4; a++) {
        float2 w = twy[yl][4 * kyg + a];
        float4 va = ((const float4*)&us[l][a][yl][4 * kzg])[0];
        float4 vb = ((const float4*)&us[l][a][yl][4 * kzg])[1];
        acc[a][0].x += w.x * va.x + w.y * va.y;  acc[a][0].y += w.x * va.y - w.y * va.x;
        acc[a][1].x += w.x * va.z + w.y * va.w;  acc[a][1].y += w.x * va.w - w.y * va.z;
        acc[a][2].x += w.x * vb.x + w.y * vb.y;  acc[a][2].y += w.x * vb.y - w.y * vb.x;
        acc[a][3].x += w.x * vb.z + w.y * vb.w;  acc[a][3].y += w.x * vb.w - w.y * vb.z;
      }
    }
  }
#pragma unroll
  for (int a = 0; a < 4; a++) {
    size_t base = ((size_t)(lineBase + l) * MXY + 4 * kyg + a) * 16 + 4 * kzg;
    ((float4*)&X2g[base])[0] = make_float4(acc[a][0].x, acc[a][0].y, acc[a][1].x, acc[a][1].y);
    ((float4*)&X2g[base])[1] = make_float4(acc[a][2].x, acc[a][2].y, acc[a][3].x, acc[a][3].y);
  }
}

// ---------------- S3: x-DFT, complex, 32 kx modes, folded (unchanged) --------
__global__ void __launch_bounds__(256) k_s3() {
  __shared__ __align__(16) float2 sA[96][16];
  __shared__ __align__(16) float2 dA[96][16];
  __shared__ float2 Tml[NSZ];
  int c = blockIdx.x >> 5, ky = blockIdx.x & 31;
  int tid = threadIdx.x;
  int kx = tid & 31, kzp = tid >> 5;

  for (int i = tid; i < NSZ; i += 256) Tml[i] = Tm[i];
  for (int i = tid; i < 96 * 8; i += 256) {
    int xx = i >> 3, u = i & 7;
    float4 a = ((const float4*)&X2g[(((size_t)c * NSZ + xx) * MXY + ky) * 16])[u];
    float4 b = ((const float4*)&X2g[(((size_t)c * NSZ + xx + 96) * MXY + ky) * 16])[u];
    ((float4*)&sA[xx][0])[u] = make_float4(a.x + b.x, a.y + b.y, a.z + b.z, a.w + b.w);
    ((float4*)&dA[xx][0])[u] = make_float4(a.x - b.x, a.y - b.y, a.z - b.z, a.w - b.w);
  }
  __syncthreads();

  const float2* vb = (kx & 1) ? &dA[0][0] : &sA[0][0];
  int kf = kmap(kx), p = 0;
  float2 a0 = make_float2(0.f, 0.f), a1 = make_float2(0.f, 0.f);
#pragma unroll 4
  for (int xx = 0; xx < 96; xx++) {
    float2 t = Tml[p];
    float4 v = *(const float4*)(vb + xx * 16 + 2 * kzp);
    a0.x += t.x * v.x + t.y * v.y;  a0.y += t.x * v.y - t.y * v.x;
    a1.x += t.x * v.z + t.y * v.w;  a1.y += t.x * v.w - t.y * v.z;
    p += kf; if (p >= NSZ) p -= NSZ;
  }
  size_t base = (((size_t)c * MXY + kx) * MXY + ky) * 16 + 2 * kzp;
  ((float4*)&X3g[base])[0] = make_float4(a0.x, a0.y, a1.x, a1.y);
}

// ---------------- Mix: per-mode 16x16 complex channel mix (unchanged) --------
__global__ void __launch_bounds__(256) k_mix(const float* __restrict__ wr,
                                             const float* __restrict__ wi) {
  __shared__ float2 xin[16][16];
  int kx = blockIdx.x >> 5, ky = blockIdx.x & 31;
  int tid = threadIdx.x;
  int kz = tid & 15, o = tid >> 4;
  {
    int i = tid >> 4, z = tid & 15;
    xin[i][z] = X3g[(((size_t)i * MXY + kx) * MXY + ky) * 16 + z];
  }
  __syncthreads();
  int q = (kx >= 16 ? 1 : 0) + (ky >= 16 ? 2 : 0);
  int mx = kx & 15, my = ky & 15;
  int moff = mx * 256 + my * 16 + kz;
  float2 acc = make_float2(0.f, 0.f);
#pragma unroll
  for (int i = 0; i < 16; i++) {
    int widx = ((q * 16 + i) * 16 + o) * 4096 + moff;
    float wrv = wr[widx], wiv = wi[widx];
    float2 xv = xin[i][kz];
    acc.x += xv.x * wrv - xv.y * wiv;
    acc.y += xv.x * wiv + xv.y * wrv;
  }
  Y3g[(((size_t)o * MXY + kx) * MXY + ky) * 16 + kz] = acc;
}

// ---------------- I1: inverse x, even/odd folded (unchanged) -----------------
__global__ void __launch_bounds__(192) k_i1() {
  __shared__ __align__(16) float2 ysd[2][32][16];
  __shared__ float2 Tml[NSZ];
  int c = blockIdx.x >> 4, kyp = blockIdx.x & 15;
  int tid = threadIdx.x;
  int h = tid / 96, x = tid % 96;
  int ky = 2 * kyp + h;

  for (int i = tid; i < NSZ; i += 192) Tml[i] = Tm[i];
  for (int i = tid; i < 1024; i += 192) {
    int hh = i >> 9, r = i & 511;
    ysd[hh][r >> 4][r & 15] =
        Y3g[(((size_t)c * MXY + (r >> 4)) * MXY + (2 * kyp + hh)) * 16 + (r & 15)];
  }
  __syncthreads();

  float2 E[16], O[16];
#pragma unroll
  for (int z = 0; z < 16; z++) { E[z] = make_float2(0.f, 0.f); O[z] = make_float2(0.f, 0.f); }

  int p = 0;
#pragma unroll 2
  for (int kx = 0; kx < 16; kx += 2) {
    float2 te = Tml[p];
    int p2 = p + x; if (p2 >= NSZ) p2 -= NSZ;
    float2 to = Tml[p2];
    p = p2 + x; if (p >= NSZ) p -= NSZ;
    const float4* ye = (const float4*)&ysd[h][kx][0];
    const float4* yo = (const float4*)&ysd[h][kx + 1][0];
#pragma unroll
    for (int qq = 0; qq < 8; qq++) {
      float4 a = ye[qq], b = yo[qq];
      E[2*qq].x   += te.x*a.x - te.y*a.y;  E[2*qq].y   += te.x*a.y + te.y*a.x;
      E[2*qq+1].x += te.x*a.z - te.y*a.w;  E[2*qq+1].y += te.x*a.w + te.y*a.z;
      O[2*qq].x   += to.x*b.x - to.y*b.y;  O[2*qq].y   += to.x*b.y + to.y*b.x;
      O[2*qq+1].x += to.x*b.z - to.y*b.w;  O[2*qq+1].y += to.x*b.w + to.y*b.z;
    }
  }
  p = (176 * x) % NSZ;
#pragma unroll 2
  for (int kx = 16; kx < 32; kx += 2) {
    float2 te = Tml[p];
    int p2 = p + x; if (p2 >= NSZ) p2 -= NSZ;
    float2 to = Tml[p2];
    p = p2 + x; if (p >= NSZ) p -= NSZ;
    const float4* ye = (const float4*)&ysd[h][kx][0];
    const float4* yo = (const float4*)&ysd[h][kx + 1][0];
#pragma unroll
    for (int qq = 0; qq < 8; qq++) {
      float4 a = ye[qq], b = yo[qq];
      E[2*qq].x   += te.x*a.x - te.y*a.y;  E[2*qq].y   += te.x*a.y + te.y*a.x;
      E[2*qq+1].x += te.x*a.z - te.y*a.w;  E[2*qq+1].y += te.x*a.w + te.y*a.z;
      O[2*qq].x   += to.x*b.x - to.y*b.y;  O[2*qq].y   += to.x*b.y + to.y*b.x;
      O[2*qq+1].x += to.x*b.z - to.y*b.w;  O[2*qq+1].y += to.x*b.w + to.y*b.z;
    }
  }

  float4* d0 = (float4*)&Y2g[(((size_t)c * NSZ + x) * MXY + ky) * 16];
  float4* d1 = (float4*)&Y2g[(((size_t)c * NSZ + x + 96) * MXY + ky) * 16];
#pragma unroll
  for (int qq = 0; qq < 8; qq++) {
    d0[qq] = make_float4(E[2*qq].x + O[2*qq].x,   E[2*qq].y + O[2*qq].y,
                         E[2*qq+1].x + O[2*qq+1].x, E[2*qq+1].y + O[2*qq+1].y);
    d1[qq] = make_float4(E[2*qq].x - O[2*qq].x,   E[2*qq].y - O[2*qq].y,
                         E[2*qq+1].x - O[2*qq+1].x, E[2*qq+1].y - O[2*qq+1].y);
  }
}

// ---------------- I2: inverse y, quad fold ------------------------------------
// E_c[t] = sum_{ky mod4=c} Y[ky] w^{+Kt}, t<48; out[t]=P+Q, out[t+96]=P-Q,
// out[t+48]=M+iR, out[t+144]=M-iR; P=E0+E2, M=E0-E2, Q=E1+E3, R=E1-E3.
// block: 384 thr = 4 lines x 48 t x 2 kz-halves
__global__ void __launch_bounds__(384) k_i2() {
  __shared__ __align__(16) float2 ysd[4][32][16];
  __shared__ float2 Tml[NSZ];
  int tid = threadIdx.x;
  int l = tid / 96;
  int r = tid % 96;
  int t = r >> 1, h = r & 1;
  size_t lineBase = (size_t)blockIdx.x * 4;

  for (int i = tid; i < NSZ; i += 384) Tml[i] = Tm[i];
  for (int i = tid; i < 1024; i += 384) {
    int li = i >> 8, rem = i & 255;
    ((float4*)&ysd[li][0][0])[rem] = ((const float4*)&Y2g[(lineBase + li) * 512])[rem];
  }
  __syncthreads();

  float2 E[4][8];
#pragma unroll
  for (int a = 0; a < 4; a++)
#pragma unroll
    for (int b = 0; b < 8; b++) E[a][b] = make_float2(0.f, 0.f);

  int p = 0;
#pragma unroll
  for (int ky = 0; ky < 16; ky++) {
    float2 w = Tml[p];
    const int cc = ky & 3;
    const float4* yp = (const float4*)&ysd[l][ky][8 * h];
    float4 y0 = yp[0], y1 = yp[1], y2 = yp[2], y3 = yp[3];
    E[cc][0].x += w.x*y0.x - w.y*y0.y;  E[cc][0].y += w.x*y0.y + w.y*y0.x;
    E[cc][1].x += w.x*y0.z - w.y*y0.w;  E[cc][1].y += w.x*y0.w + w.y*y0.z;
    E[cc][2].x += w.x*y1.x - w.y*y1.y;  E[cc][2].y += w.x*y1.y + w.y*y1.x;
    E[cc][3].x += w.x*y1.z - w.y*y1.w;  E[cc][3].y += w.x*y1.w + w.y*y1.z;
    E[cc][4].x += w.x*y2.x - w.y*y2.y;  E[cc][4].y += w.x*y2.y + w.y*y2.x;
    E[cc][5].x += w.x*y2.z - w.y*y2.w;  E[cc][5].y += w.x*y2.w + w.y*y2.z;
    E[cc][6].x += w.x*y3.x - w.y*y3.y;  E[cc][6].y += w.x*y3.y + w.y*y3.x;
    E[cc][7].x += w.x*y3.z - w.y*y3.w;  E[cc][7].y += w.x*y3.w + w.y*y3.z;
    p += t; if (p >= NSZ) p -= NSZ;
  }
  p = (176 * t) % NSZ;
#pragma unroll
  for (int ky = 16; ky < 32; ky++) {
    float2 w = Tml[p];
    const int cc = ky & 3;
    const float4* yp = (const float4*)&ysd[l][ky][8 * h];
    float4 y0 = yp[0], y1 = yp[1], y2 = yp[2], y3 = yp[3];
    E[cc][0].x += w.x*y0.x - w.y*y0.y;  E[cc][0].y += w.x*y0.y + w.y*y0.x;
    E[cc][1].x += w.x*y0.z - w.y*y0.w;  E[cc][1].y += w.x*y0.w + w.y*y0.z;
    E[cc][2].x += w.x*y1.x - w.y*y1.y;  E[cc][2].y += w.x*y1.y + w.y*y1.x;
    E[cc][3].x += w.x*y1.z - w.y*y1.w;  E[cc][3].y += w.x*y1.w + w.y*y1.z;
    E[cc][4].x += w.x*y2.x - w.y*y2.y;  E[cc][4].y += w.x*y2.y + w.y*y2.x;
    E[cc][5].x += w.x*y2.z - w.y*y2.w;  E[cc][5].y += w.x*y2.w + w.y*y2.z;
    E[cc][6].x += w.x*y3.x - w.y*y3.y;  E[cc][6].y += w.x*y3.y + w.y*y3.x;
    E[cc][7].x += w.x*y3.z - w.y*y3.w;  E[cc][7].y += w.x*y3.w + w.y*y3.z;
    p += t; if (p >= NSZ) p -= NSZ;
  }

  size_t ob = ((lineBase + l) * (size_t)NSZ + t) * 16 + 8 * h;
  float4* o0 = (float4*)&Y1g[ob];
  float4* o1 = (float4*)&Y1g[ob + (size_t)48 * 16];
  float4* o2 = (float4*)&Y1g[ob + (size_t)96 * 16];
  float4* o3 = (float4*)&Y1g[ob + (size_t)144 * 16];
#pragma unroll
  for (int bb = 0; bb < 4; bb++) {
    int b0 = 2 * bb, b1 = 2 * bb + 1;
    float2 P0 = make_float2(E[0][b0].x + E[2][b0].x, E[0][b0].y + E[2][b0].y);
    float2 M0 = make_float2(E[0][b0].x - E[2][b0].x, E[0][b0].y - E[2][b0].y);
    float2 Q0 = make_float2(E[1][b0].x + E[3][b0].x, E[1][b0].y + E[3][b0].y);
    float2 R0 = make_float2(E[1][b0].x - E[3][b0].x, E[1][b0].y - E[3][b0].y);
    float2 P1 = make_float2(E[0][b1].x + E[2][b1].x, E[0][b1].y + E[2][b1].y);
    float2 M1 = make_float2(E[0][b1].x - E[2][b1].x, E[0][b1].y - E[2][b1].y);
    float2 Q1 = make_float2(E[1][b1].x + E[3][b1].x, E[1][b1].y + E[3][b1].y);
    float2 R1 = make_float2(E[1][b1].x - E[3][b1].x, E[1][b1].y - E[3][b1].y);
    o0[bb] = make_float4(P0.x + Q0.x, P0.y + Q0.y, P1.x + Q1.x, P1.y + Q1.y);
    o1[bb] = make_float4(M0.x - R0.y, M0.y + R0.x, M1.x - R1.y, M1.y + R1.x);
    o2[bb] = make_float4(P0.x - Q0.x, P0.y - Q0.y, P1.x - Q1.x, P1.y - Q1.y);
    o3[bb] = make_float4(M0.x + R0.y, M0.y - R0.x, M1.x + R1.y, M1.y - R1.x);
  }
}

// ---------------- I3: inverse z C2R, quad fold --------------------------------
// Ce/Se (k even), Co/So (k odd) over z<48:
//   out[z]      = (Ce+Co) - (Se+So)        out[192-z] = (Ce+Co) + (Se+So)  [z>0]
//   out[z+96]   = (Ce-Co) - (Se-So)        out[96-z]  = (Ce-Co) + (Se-So)  [z>0]
//   out[48] = E48 - O48,  out[144] = E48 + O48
// block: 256 thr = zx(16) x ry(16); 64 rows; thread: 4 rows x 3 z
__global__ void __launch_bounds__(256) k_i3(float* __restrict__ out) {
  __shared__ __align__(16) float2 ys[64][16];   // 8 KB
  __shared__ float twc[16][48], twsn[16][48];   // 6 KB
  size_t rowBase = (size_t)blockIdx.x * 64;
  int tid = threadIdx.x;
  int zx = tid & 15, ry = tid >> 4;

  for (int i = tid; i < 512; i += 256)
    ((float4*)ys)[i] = ((const float4*)&Y1g[rowBase * 16])[i];

  const float inv = 1.0f / (192.0f * 192.0f * 192.0f);
  for (int i = tid; i < 768; i += 256) {
    int k = i / 48, z = i % 48;
    float a = (k == 0) ? inv : 2.0f * inv;
    float2 tv = Tm[(k * z) % NSZ];
    twc[k][z] = a * tv.x;
    twsn[k][z] = a * tv.y;
  }
  __syncthreads();

  float Ce[4][3], Se[4][3], Co[4][3], So[4][3], E48[4], O48[4];
#pragma unroll
  for (int j = 0; j < 4; j++) {
    E48[j] = 0.f; O48[j] = 0.f;
#pragma unroll
    for (int m = 0; m < 3; m++) { Ce[j][m] = 0.f; Se[j][m] = 0.f; Co[j][m] = 0.f; So[j][m] = 0.f; }
  }

#pragma unroll
  for (int m = 0; m < 8; m++) {
    const int k = 2 * m;
    float tc0 = twc[k][zx], tc1 = twc[k][zx + 16], tc2 = twc[k][zx + 32];
    float ts0 = twsn[k][zx], ts1 = twsn[k][zx + 16], ts2 = twsn[k][zx + 32];
    float ec = ((k == 0) ? inv : 2.f * inv) * ((m & 1) ? -1.f : 1.f);
#pragma unroll
    for (int j = 0; j < 4; j++) {
      float2 yv = ys[ry * 4 + j][k];
      Ce[j][0] += yv.x * tc0;  Se[j][0] += yv.y * ts0;
      Ce[j][1] += yv.x * tc1;  Se[j][1] += yv.y * ts1;
      Ce[j][2] += yv.x * tc2;  Se[j][2] += yv.y * ts2;
      E48[j] += yv.x * ec;
    }
  }
#pragma unroll
  for (int m = 0; m < 8; m++) {
    const int k = 2 * m + 1;
    float tc0 = twc[k][zx], tc1 = twc[k][zx + 16], tc2 = twc[k][zx + 32];
    float ts0 = twsn[k][zx], ts1 = twsn[k][zx + 16], ts2 = twsn[k][zx + 32];
    float oc = 2.f * inv * ((m & 1) ? -1.f : 1.f);
#pragma unroll
    for (int j = 0; j < 4; j++) {
      float2 yv = ys[ry * 4 + j][k];
      Co[j][0] += yv.x * tc0;  So[j][0] += yv.y * ts0;
      Co[j][1] += yv.x * tc1;  So[j][1] += yv.y * ts1;
      Co[j][2] += yv.x * tc2;  So[j][2] += yv.y * ts2;
      O48[j] += yv.y * oc;
    }
  }

#pragma unroll
  for (int j = 0; j < 4; j++) {
    size_t base = (rowBase + ry * 4 + j) * (size_t)NSZ;
#pragma unroll
    for (int mm = 0; mm < 3; mm++) {
      int z = zx + 16 * mm;
      float Cp = Ce[j][mm] + Co[j][mm], Sp = Se[j][mm] + So[j][mm];
      float Cm = Ce[j][mm] - Co[j][mm], Sm = Se[j][mm] - So[j][mm];
      out[base + z] = Cp - Sp;
      out[base + 96 + z] = Cm - Sm;
      if (z) {
        out[base + 192 - z] = Cp + Sp;
        out[base + 96 - z] = Cm + Sm;
      }
    }
    if (zx == 0) {
      out[base + 48] = E48[j] - O48[j];
      out[base + 144] = E48[j] + O48[j];
    }
  }
}

// ---------------- launch -------------------------------------------------------
extern "C" void kernel_launch(void* const* d_in, const int* in_sizes, int n_in,
                              void* d_out, int out_size) {
  (void)in_sizes; (void)n_in; (void)out_size;
  const float* x  = (const float*)d_in[0];
  const float* wr = (const float*)d_in[1];
  const float* wi = (const float*)d_in[2];

  k_init<<<1, 192>>>();
  k_s1 <<<NROW / 256, 128>>>(x);            // 2304 blocks
  k_s2 <<<NLINE / 4, 128>>>();              // 768 blocks
  k_s3 <<<NC * MXY, 256>>>();               // 512 blocks
  k_mix<<<MXY * MXY, 256>>>(wr, wi);        // 1024 blocks
  k_i1 <<<NC * 16, 192>>>();                // 256 blocks
  k_i2 <<<NLINE / 4, 384>>>();              // 768 blocks
  k_i3 <<<NROW / 64, 256>>>((float*)d_out); // 9216 blocks
}

// round 16
// speedup vs baseline: 1.1480x; 1.1480x over previous
#include <cuda_runtime.h>
#include <math.h>

#define NSZ 192
#define NC  16
#define MXY 32
#define NLINE (NC*NSZ)       // 3072
#define NROW  (NC*NSZ*NSZ)   // 589824

// ---------------- twiddle master table + scratch -----------------------------
static __device__ float2 Tm[NSZ];   // (cos, sin) of 2*pi*p/192

static __device__ __align__(16) float2 X1g[(size_t)NROW * 16];            // (c,x,y,kz)
static __device__ __align__(16) float2 X2g[(size_t)NLINE * MXY * 16];     // (c,x,ky,kz)
static __device__ __align__(16) float2 X3g[(size_t)NC * MXY * MXY * 16];  // (i,kx,ky,kz)
static __device__ __align__(16) float2 Y3g[(size_t)NC * MXY * MXY * 16];  // (o,kx,ky,kz)
static __device__ __align__(16) float2 Y2g[(size_t)NLINE * MXY * 16];     // (c,x,ky,kz)
static __device__ __align__(16) float2 Y1g[(size_t)NROW * 16];            // (c,x,y,kz)

__device__ __forceinline__ int kmap(int j) { return j < 16 ? j : j + 160; }

__global__ void k_init() {
  int p = threadIdx.x;
  if (p < NSZ) {
    float s, c;
    sincosf(6.283185307179586f * (float)p / 192.0f, &s, &c);
    Tm[p] = make_float2(c, s);
  }
}

// ---------------- S1: z-DFT, real -> 16 complex modes, radix-2 folded --------
// (R14 version: coalesced float4 loads, single +-96 fold)
__global__ void __launch_bounds__(128) k_s1(const float* __restrict__ xg) {
  __shared__ float ss[16][257];        // sum   [z_local][row]
  __shared__ float dd[16][257];        // diff
  __shared__ float2 tws[16][16];       // (cos, sin) [z_local][k]
  int tid = threadIdx.x;
  int tx = tid & 3, ty = tid >> 2;
  int rowBase = blockIdx.x * 256;

  float2 acc[8][4];
#pragma unroll
  for (int j = 0; j < 8; j++)
#pragma unroll
    for (int q = 0; q < 4; q++) acc[j][q] = make_float2(0.f, 0.f);

  for (int zc = 0; zc < 96; zc += 16) {
    __syncthreads();
    for (int i = tid; i < 256; i += 128) {
      int zl = i >> 4, k = i & 15;
      int p = (k * (zc + zl)) % NSZ;
      tws[zl][k] = Tm[p];
    }
    for (int i = tid; i < 1024; i += 128) {   // 256 rows x 4 float4
      int row = i >> 2, u = i & 3;
      const float* rp = xg + (size_t)(rowBase + row) * NSZ + zc + 4 * u;
      float4 a = *(const float4*)rp;
      float4 b = *(const float4*)(rp + 96);
      int zb = 4 * u;
      ss[zb + 0][row] = a.x + b.x;  dd[zb + 0][row] = a.x - b.x;
      ss[zb + 1][row] = a.y + b.y;  dd[zb + 1][row] = a.y - b.y;
      ss[zb + 2][row] = a.z + b.z;  dd[zb + 2][row] = a.z - b.z;
      ss[zb + 3][row] = a.w + b.w;  dd[zb + 3][row] = a.w - b.w;
    }
    __syncthreads();
#pragma unroll 4
    for (int zl = 0; zl < 16; zl++) {
      float2 t0 = tws[zl][4 * tx + 0];
      float2 t1 = tws[zl][4 * tx + 1];
      float2 t2 = tws[zl][4 * tx + 2];
      float2 t3 = tws[zl][4 * tx + 3];
      const float* sr = &ss[zl][ty];
      const float* dr = &dd[zl][ty];
#pragma unroll
      for (int j = 0; j < 8; j++) {
        float sv = sr[32 * j], dv = dr[32 * j];
        acc[j][0].x += sv * t0.x;  acc[j][0].y -= sv * t0.y;   // k even
        acc[j][1].x += dv * t1.x;  acc[j][1].y -= dv * t1.y;   // k odd
        acc[j][2].x += sv * t2.x;  acc[j][2].y -= sv * t2.y;
        acc[j][3].x += dv * t3.x;  acc[j][3].y -= dv * t3.y;
      }
    }
  }
#pragma unroll
  for (int j = 0; j < 8; j++) {
    size_t base = (size_t)(rowBase + ty + 32 * j) * 16 + 4 * tx;
    ((float4*)&X1g[base])[0] = make_float4(acc[j][0].x, acc[j][0].y, acc[j][1].x, acc[j][1].y);
    ((float4*)&X1g[base])[1] = make_float4(acc[j][2].x, acc[j][2].y, acc[j][3].x, acc[j][3].y);
  }
}

// ---------------- S2: y-DFT, complex, 32 ky modes, quad fold (R15) -----------
// X[K] = sum_{t<48} u_{K mod 4}[t] w^{Kt}; u0=s1+s2, u2=s1-s2, u1=d1-i*d2, u3=d1+i*d2
// block: 128 thr = 4 lines x (kyg 8 x kzg 4); thread tile 4 ky (classes 0..3) x 4 kz
__global__ void __launch_bounds__(128) k_s2() {
  __shared__ __align__(16) float2 us[4][4][12][16];  // [line][cls][yl][kz]
  __shared__ float2 twy[12][32];
  int tid = threadIdx.x;
  int l = tid >> 5, lane = tid & 31;
  int kyg = lane >> 2, kzg = lane & 3;
  int lineBase = blockIdx.x * 4;

  float2 acc[4][4];
#pragma unroll
  for (int a = 0; a < 4; a++)
#pragma unroll
    for (int b = 0; b < 4; b++) acc[a][b] = make_float2(0.f, 0.f);

  for (int yc = 0; yc < 48; yc += 12) {
    __syncthreads();
    for (int i = tid; i < 12 * 32; i += 128) {
      int yl = i >> 5, ky = i & 31;
      twy[yl][ky] = Tm[(kmap(ky) * (yc + yl)) % NSZ];
    }
    for (int i = tid; i < 384; i += 128) {
      int li = i / 96, rem = i % 96;
      int yl = rem >> 3, v = rem & 7;
      size_t rb = ((size_t)(lineBase + li) * NSZ + yc + yl) * 16;
      float4 A = ((const float4*)&X1g[rb])[v];
      float4 B = ((const float4*)&X1g[rb + (size_t)48 * 16])[v];
      float4 C = ((const float4*)&X1g[rb + (size_t)96 * 16])[v];
      float4 D = ((const float4*)&X1g[rb + (size_t)144 * 16])[v];
      float4 s1 = make_float4(A.x + C.x, A.y + C.y, A.z + C.z, A.w + C.w);
      float4 s2 = make_float4(B.x + D.x, B.y + D.y, B.z + D.z, B.w + D.w);
      float4 d1 = make_float4(A.x - C.x, A.y - C.y, A.z - C.z, A.w - C.w);
      float4 d2 = make_float4(B.x - D.x, B.y - D.y, B.z - D.z, B.w - D.w);
      ((float4*)&us[li][0][yl][0])[v] =
          make_float4(s1.x + s2.x, s1.y + s2.y, s1.z + s2.z, s1.w + s2.w);
      ((float4*)&us[li][2][yl][0])[v] =
          make_float4(s1.x - s2.x, s1.y - s2.y, s1.z - s2.z, s1.w - s2.w);
      ((float4*)&us[li][1][yl][0])[v] =
          make_float4(d1.x + d2.y, d1.y - d2.x, d1.z + d2.w, d1.w - d2.z);
      ((float4*)&us[li][3][yl][0])[v] =
          make_float4(d1.x - d2.y, d1.y + d2.x, d1.z - d2.w, d1.w + d2.z);
    }
    __syncthreads();
#pragma unroll 2
    for (int yl = 0; yl < 12; yl++) {
#pragma unroll
      for (int a = 0; a < 4; a++) {
        float2 w = twy[yl][4 * kyg + a];
        float4 va = ((const float4*)&us[l][a][yl][4 * kzg])[0];
        float4 vb = ((const float4*)&us[l][a][yl][4 * kzg])[1];
        acc[a][0].x += w.x * va.x + w.y * va.y;  acc[a][0].y += w.x * va.y - w.y * va.x;
        acc[a][1].x += w.x * va.z + w.y * va.w;  acc[a][1].y += w.x * va.w - w.y * va.z;
        acc[a][2].x += w.x * vb.x + w.y * vb.y;  acc[a][2].y += w.x * vb.y - w.y * vb.x;
        acc[a][3].x += w.x * vb.z + w.y * vb.w;  acc[a][3].y += w.x * vb.w - w.y * vb.z;
      }
    }
  }
#pragma unroll
  for (int a = 0; a < 4; a++) {
    size_t base = ((size_t)(lineBase + l) * MXY + 4 * kyg + a) * 16 + 4 * kzg;
    ((float4*)&X2g[base])[0] = make_float4(acc[a][0].x, acc[a][0].y, acc[a][1].x, acc[a][1].y);
    ((float4*)&X2g[base])[1] = make_float4(acc[a][2].x, acc[a][2].y, acc[a][3].x, acc[a][3].y);
  }
}

// ---------------- S3: x-DFT, complex, 32 kx modes, folded --------------------
__global__ void __launch_bounds__(256) k_s3() {
  __shared__ __align__(16) float2 sA[96][16];
  __shared__ __align__(16) float2 dA[96][16];
  __shared__ float2 Tml[NSZ];
  int c = blockIdx.x >> 5, ky = blockIdx.x & 31;
  int tid = threadIdx.x;
  int kx = tid & 31, kzp = tid >> 5;

  for (int i = tid; i < NSZ; i += 256) Tml[i] = Tm[i];
  for (int i = tid; i < 96 * 8; i += 256) {
    int xx = i >> 3, u = i & 7;
    float4 a = ((const float4*)&X2g[(((size_t)c * NSZ + xx) * MXY + ky) * 16])[u];
    float4 b = ((const float4*)&X2g[(((size_t)c * NSZ + xx + 96) * MXY + ky) * 16])[u];
    ((float4*)&sA[xx][0])[u] = make_float4(a.x + b.x, a.y + b.y, a.z + b.z, a.w + b.w);
    ((float4*)&dA[xx][0])[u] = make_float4(a.x - b.x, a.y - b.y, a.z - b.z, a.w - b.w);
  }
  __syncthreads();

  const float2* vb = (kx & 1) ? &dA[0][0] : &sA[0][0];
  int kf = kmap(kx), p = 0;
  float2 a0 = make_float2(0.f, 0.f), a1 = make_float2(0.f, 0.f);
#pragma unroll 4
  for (int xx = 0; xx < 96; xx++) {
    float2 t = Tml[p];
    float4 v = *(const float4*)(vb + xx * 16 + 2 * kzp);
    a0.x += t.x * v.x + t.y * v.y;  a0.y += t.x * v.y - t.y * v.x;
    a1.x += t.x * v.z + t.y * v.w;  a1.y += t.x * v.w - t.y * v.z;
    p += kf; if (p >= NSZ) p -= NSZ;
  }
  size_t base = (((size_t)c * MXY + kx) * MXY + ky) * 16 + 2 * kzp;
  ((float4*)&X3g[base])[0] = make_float4(a0.x, a0.y, a1.x, a1.y);
}

// ---------------- Mix: per-mode 16x16 complex channel mix --------------------
__global__ void __launch_bounds__(256) k_mix(const float* __restrict__ wr,
                                             const float* __restrict__ wi) {
  __shared__ float2 xin[16][16];
  int kx = blockIdx.x >> 5, ky = blockIdx.x & 31;
  int tid = threadIdx.x;
  int kz = tid & 15, o = tid >> 4;
  {
    int i = tid >> 4, z = tid & 15;
    xin[i][z] = X3g[(((size_t)i * MXY + kx) * MXY + ky) * 16 + z];
  }
  __syncthreads();
  int q = (kx >= 16 ? 1 : 0) + (ky >= 16 ? 2 : 0);
  int mx = kx & 15, my = ky & 15;
  int moff = mx * 256 + my * 16 + kz;
  float2 acc = make_float2(0.f, 0.f);
#pragma unroll
  for (int i = 0; i < 16; i++) {
    int widx = ((q * 16 + i) * 16 + o) * 4096 + moff;
    float wrv = wr[widx], wiv = wi[widx];
    float2 xv = xin[i][kz];
    acc.x += xv.x * wrv - xv.y * wiv;
    acc.y += xv.x * wiv + xv.y * wrv;
  }
  Y3g[(((size_t)o * MXY + kx) * MXY + ky) * 16 + kz] = acc;
}

// ---------------- I1: inverse x (32 modes -> 192 x), even/odd folded ---------
__global__ void __launch_bounds__(192) k_i1() {
  __shared__ __align__(16) float2 ysd[2][32][16];
  __shared__ float2 Tml[NSZ];
  int c = blockIdx.x >> 4, kyp = blockIdx.x & 15;
  int tid = threadIdx.x;
  int h = tid / 96, x = tid % 96;
  int ky = 2 * kyp + h;

  for (int i = tid; i < NSZ; i += 192) Tml[i] = Tm[i];
  for (int i = tid; i < 1024; i += 192) {
    int hh = i >> 9, r = i & 511;
    ysd[hh][r >> 4][r & 15] =
        Y3g[(((size_t)c * MXY + (r >> 4)) * MXY + (2 * kyp + hh)) * 16 + (r & 15)];
  }
  __syncthreads();

  float2 E[16], O[16];
#pragma unroll
  for (int z = 0; z < 16; z++) { E[z] = make_float2(0.f, 0.f); O[z] = make_float2(0.f, 0.f); }

  int p = 0;
#pragma unroll 2
  for (int kx = 0; kx < 16; kx += 2) {
    float2 te = Tml[p];
    int p2 = p + x; if (p2 >= NSZ) p2 -= NSZ;
    float2 to = Tml[p2];
    p = p2 + x; if (p >= NSZ) p -= NSZ;
    const float4* ye = (const float4*)&ysd[h][kx][0];
    const float4* yo = (const float4*)&ysd[h][kx + 1][0];
#pragma unroll
    for (int qq = 0; qq < 8; qq++) {
      float4 a = ye[qq], b = yo[qq];
      E[2*qq].x   += te.x*a.x - te.y*a.y;  E[2*qq].y   += te.x*a.y + te.y*a.x;
      E[2*qq+1].x += te.x*a.z - te.y*a.w;  E[2*qq+1].y += te.x*a.w + te.y*a.z;
      O[2*qq].x   += to.x*b.x - to.y*b.y;  O[2*qq].y   += to.x*b.y + to.y*b.x;
      O[2*qq+1].x += to.x*b.z - to.y*b.w;  O[2*qq+1].y += to.x*b.w + to.y*b.z;
    }
  }
  p = (176 * x) % NSZ;
#pragma unroll 2
  for (int kx = 16; kx < 32; kx += 2) {
    float2 te = Tml[p];
    int p2 = p + x; if (p2 >= NSZ) p2 -= NSZ;
    float2 to = Tml[p2];
    p = p2 + x; if (p >= NSZ) p -= NSZ;
    const float4* ye = (const float4*)&ysd[h][kx][0];
    const float4* yo = (const float4*)&ysd[h][kx + 1][0];
#pragma unroll
    for (int qq = 0; qq < 8; qq++) {
      float4 a = ye[qq], b = yo[qq];
      E[2*qq].x   += te.x*a.x - te.y*a.y;  E[2*qq].y   += te.x*a.y + te.y*a.x;
      E[2*qq+1].x += te.x*a.z - te.y*a.w;  E[2*qq+1].y += te.x*a.w + te.y*a.z;
      O[2*qq].x   += to.x*b.x - to.y*b.y;  O[2*qq].y   += to.x*b.y + to.y*b.x;
      O[2*qq+1].x += to.x*b.z - to.y*b.w;  O[2*qq+1].y += to.x*b.w + to.y*b.z;
    }
  }

  float4* d0 = (float4*)&Y2g[(((size_t)c * NSZ + x) * MXY + ky) * 16];
  float4* d1 = (float4*)&Y2g[(((size_t)c * NSZ + x + 96) * MXY + ky) * 16];
#pragma unroll
  for (int qq = 0; qq < 8; qq++) {
    d0[qq] = make_float4(E[2*qq].x + O[2*qq].x,   E[2*qq].y + O[2*qq].y,
                         E[2*qq+1].x + O[2*qq+1].x, E[2*qq+1].y + O[2*qq+1].y);
    d1[qq] = make_float4(E[2*qq].x - O[2*qq].x,   E[2*qq].y - O[2*qq].y,
                         E[2*qq+1].x - O[2*qq+1].x, E[2*qq+1].y - O[2*qq+1].y);
  }
}

// ---------------- I2: inverse y (32 modes -> 192 y), even/odd folded (R14) ---
__global__ void __launch_bounds__(192) k_i2() {
  __shared__ __align__(16) float2 ysd[2][32][16];
  __shared__ float2 Tml[NSZ];
  int tid = threadIdx.x;
  int h = tid / 96, y = tid % 96;
  size_t line = (size_t)blockIdx.x * 2 + h;

  for (int i = tid; i < NSZ; i += 192) Tml[i] = Tm[i];
  for (int i = tid; i < 1024; i += 192) {
    int hh = i >> 9, r = i & 511;
    ysd[hh][r >> 4][r & 15] = Y2g[((size_t)blockIdx.x * 2 + hh) * 512 + r];
  }
  __syncthreads();

  float2 E[16], O[16];
#pragma unroll
  for (int z = 0; z < 16; z++) { E[z] = make_float2(0.f, 0.f); O[z] = make_float2(0.f, 0.f); }

  int p = 0;
#pragma unroll 2
  for (int ky = 0; ky < 16; ky += 2) {
    float2 te = Tml[p];
    int p2 = p + y; if (p2 >= NSZ) p2 -= NSZ;
    float2 to = Tml[p2];
    p = p2 + y; if (p >= NSZ) p -= NSZ;
    const float4* ye = (const float4*)&ysd[h][ky][0];
    const float4* yo = (const float4*)&ysd[h][ky + 1][0];
#pragma unroll
    for (int qq = 0; qq < 8; qq++) {
      float4 a = ye[qq], b = yo[qq];
      E[2*qq].x   += te.x*a.x - te.y*a.y;  E[2*qq].y   += te.x*a.y + te.y*a.x;
      E[2*qq+1].x += te.x*a.z - te.y*a.w;  E[2*qq+1].y += te.x*a.w + te.y*a.z;
      O[2*qq].x   += to.x*b.x - to.y*b.y;  O[2*qq].y   += to.x*b.y + to.y*b.x;
      O[2*qq+1].x += to.x*b.z - to.y*b.w;  O[2*qq+1].y += to.x*b.w + to.y*b.z;
    }
  }
  p = (176 * y) % NSZ;
#pragma unroll 2
  for (int ky = 16; ky < 32; ky += 2) {
    float2 te = Tml[p];
    int p2 = p + y; if (p2 >= NSZ) p2 -= NSZ;
    float2 to = Tml[p2];
    p = p2 + y; if (p >= NSZ) p -= NSZ;
    const float4* ye = (const float4*)&ysd[h][ky][0];
    const float4* yo = (const float4*)&ysd[h][ky + 1][0];
#pragma unroll
    for (int qq = 0; qq < 8; qq++) {
      float4 a = ye[qq], b = yo[qq];
      E[2*qq].x   += te.x*a.x - te.y*a.y;  E[2*qq].y   += te.x*a.y + te.y*a.x;
      E[2*qq+1].x += te.x*a.z - te.y*a.w;  E[2*qq+1].y += te.x*a.w + te.y*a.z;
      O[2*qq].x   += to.x*b.x - to.y*b.y;  O[2*qq].y   += to.x*b.y + to.y*b.x;
      O[2*qq+1].x += to.x*b.z - to.y*b.w;  O[2*qq+1].y += to.x*b.w + to.y*b.z;
    }
  }

  float4* d0 = (float4*)&Y1g[(line * NSZ + y) * 16];
  float4* d1 = (float4*)&Y1g[(line * NSZ + y + 96) * 16];
#pragma unroll
  for (int qq = 0; qq < 8; qq++) {
    d0[qq] = make_float4(E[2*qq].x + O[2*qq].x,   E[2*qq].y + O[2*qq].y,
                         E[2*qq+1].x + O[2*qq+1].x, E[2*qq+1].y + O[2*qq+1].y);
    d1[qq] = make_float4(E[2*qq].x - O[2*qq].x,   E[2*qq].y - O[2*qq].y,
                         E[2*qq+1].x - O[2*qq+1].x, E[2*qq+1].y - O[2*qq+1].y);
  }
}

// ---------------- I3: inverse z C2R, quad fold (R15) -------------------------
// Ce/Se (k even), Co/So (k odd) over z<48:
//   out[z]      = (Ce+Co) - (Se+So)        out[192-z] = (Ce+Co) + (Se+So)  [z>0]
//   out[z+96]   = (Ce-Co) - (Se-So)        out[96-z]  = (Ce-Co) + (Se-So)  [z>0]
//   out[48] = E48 - O48,  out[144] = E48 + O48
// block: 256 thr = zx(16) x ry(16); 64 rows; thread: 4 rows x 3 z
__global__ void __launch_bounds__(256) k_i3(float* __restrict__ out) {
  __shared__ __align__(16) float2 ys[64][16];   // 8 KB
  __shared__ float twc[16][48], twsn[16][48];   // 6 KB
  size_t rowBase = (size_t)blockIdx.x * 64;
  int tid = threadIdx.x;
  int zx = tid & 15, ry = tid >> 4;

  for (int i = tid; i < 512; i += 256)
    ((float4*)ys)[i] = ((const float4*)&Y1g[rowBase * 16])[i];

  const float inv = 1.0f / (192.0f * 192.0f * 192.0f);
  for (int i = tid; i < 768; i += 256) {
    int k = i / 48, z = i % 48;
    float a = (k == 0) ? inv : 2.0f * inv;
    float2 tv = Tm[(k * z) % NSZ];
    twc[k][z] = a * tv.x;
    twsn[k][z] = a * tv.y;
  }
  __syncthreads();

  float Ce[4][3], Se[4][3], Co[4][3], So[4][3], E48[4], O48[4];
#pragma unroll
  for (int j = 0; j < 4; j++) {
    E48[j] = 0.f; O48[j] = 0.f;
#pragma unroll
    for (int m = 0; m < 3; m++) { Ce[j][m] = 0.f; Se[j][m] = 0.f; Co[j][m] = 0.f; So[j][m] = 0.f; }
  }

#pragma unroll
  for (int m = 0; m < 8; m++) {
    const int k = 2 * m;
    float tc0 = twc[k][zx], tc1 = twc[k][zx + 16], tc2 = twc[k][zx + 32];
    float ts0 = twsn[k][zx], ts1 = twsn[k][zx + 16], ts2 = twsn[k][zx + 32];
    float ec = ((k == 0) ? inv : 2.f * inv) * ((m & 1) ? -1.f : 1.f);
#pragma unroll
    for (int j = 0; j < 4; j++) {
      float2 yv = ys[ry * 4 + j][k];
      Ce[j][0] += yv.x * tc0;  Se[j][0] += yv.y * ts0;
      Ce[j][1] += yv.x * tc1;  Se[j][1] += yv.y * ts1;
      Ce[j][2] += yv.x * tc2;  Se[j][2] += yv.y * ts2;
      E48[j] += yv.x * ec;
    }
  }
#pragma unroll
  for (int m = 0; m < 8; m++) {
    const int k = 2 * m + 1;
    float tc0 = twc[k][zx], tc1 = twc[k][zx + 16], tc2 = twc[k][zx + 32];
    float ts0 = twsn[k][zx], ts1 = twsn[k][zx + 16], ts2 = twsn[k][zx + 32];
    float oc = 2.f * inv * ((m & 1) ? -1.f : 1.f);
#pragma unroll
    for (int j = 0; j < 4; j++) {
      float2 yv = ys[ry * 4 + j][k];
      Co[j][0] += yv.x * tc0;  So[j][0] += yv.y * ts0;
      Co[j][1] += yv.x * tc1;  So[j][1] += yv.y * ts1;
      Co[j][2] += yv.x * tc2;  So[j][2] += yv.y * ts2;
      O48[j] += yv.y * oc;
    }
  }

#pragma unroll
  for (int j = 0; j < 4; j++) {
    size_t base = (rowBase + ry * 4 + j) * (size_t)NSZ;
#pragma unroll
    for (int mm = 0; mm < 3; mm++) {
      int z = zx + 16 * mm;
      float Cp = Ce[j][mm] + Co[j][mm], Sp = Se[j][mm] + So[j][mm];
      float Cm = Ce[j][mm] - Co[j][mm], Sm = Se[j][mm] - So[j][mm];
      out[base + z] = Cp - Sp;
      out[base + 96 + z] = Cm - Sm;
      if (z) {
        out[base + 192 - z] = Cp + Sp;
        out[base + 96 - z] = Cm + Sm;
      }
    }
    if (zx == 0) {
      out[base + 48] = E48[j] - O48[j];
      out[base + 144] = E48[j] + O48[j];
    }
  }
}

// ---------------- launch -------------------------------------------------------
extern "C" void kernel_launch(void* const* d_in, const int* in_sizes, int n_in,
                              void* d_out, int out_size) {
  (void)in_sizes; (void)n_in; (void)out_size;
  const float* x  = (const float*)d_in[0];
  const float* wr = (const float*)d_in[1];
  const float* wi = (const float*)d_in[2];

  k_init<<<1, 192>>>();
  k_s1 <<<NROW / 256, 128>>>(x);            // 2304 blocks
  k_s2 <<<NLINE / 4, 128>>>();              // 768 blocks
  k_s3 <<<NC * MXY, 256>>>();               // 512 blocks
  k_mix<<<MXY * MXY, 256>>>(wr, wi);        // 1024 blocks
  k_i1 <<<NC * 16, 192>>>();                // 256 blocks
  k_i2 <<<NLINE / 2, 192>>>();              // 1536 blocks
  k_i3 <<<NROW / 64, 256>>>((float*)d_out); // 9216 blocks
}